// round 4
// baseline (speedup 1.0000x reference)
#include <cuda_runtime.h>

#define NVW   9
#define HSZ   480
#define WSZ   640
#define NPIX  (HSZ*WSZ)
#define GD    96
#define NCELL (GD*GD*GD)
#define MAXN  400000
#define BIGF  1e30f

// ---- scratch (static device globals; no allocation at runtime) ----
__device__ __align__(16) int          g_last[NCELL];
__device__ float                      g_grid[NCELL];
__device__ __align__(16) unsigned int g_dflat[NVW*NPIX];   // z-buffer, float bits (>=0)
__device__ __align__(16) float        g_nsum[NVW*NPIX*3];
__device__ __align__(16) float        g_ncnt[NVW*NPIX];
__device__ int                        g_ppix[NVW*MAXN];    // cached pixel (or -1)
__device__ float                      g_pz[NVW*MAXN];      // cached camera z
__device__ unsigned int g_dmin[NVW], g_tmin[NVW], g_dmax[NVW], g_tmax[NVW];
__device__ float        g_lsum[NVW];
__device__ int          g_vcnt[NVW];

// XLA:CPU dot (no FMA contraction, left-assoc, strict rn): ((p0*m0 + p1*m1) + p2*m2)
__device__ __forceinline__ float dotrow(const float* M, float px, float py, float pz) {
    return __fadd_rn(__fadd_rn(__fmul_rn(px, M[0]), __fmul_rn(py, M[1])),
                     __fmul_rn(pz, M[2]));
}
// u = rn( (f*x)/zs + c ), strict
__device__ __forceinline__ int proj_pix(float f, float c, float x, float zs) {
    return __float2int_rn(__fadd_rn(__fdiv_rn(__fmul_rn(f, x), zs), c));
}

// ---------------- init (vectorized; re-run every replay) -------------------
#define N4_NSUM  (NVW*NPIX*3/4)   // 2073600
#define N4_IMG   (NVW*NPIX/4)     // 691200
#define N4_LAST  (NCELL/4)        // 221184
__global__ void k_init() {
    int i = blockIdx.x * blockDim.x + threadIdx.x;
    unsigned int big = __float_as_uint(BIGF);
    float4 z4 = make_float4(0.f, 0.f, 0.f, 0.f);
    if (i < N4_NSUM) reinterpret_cast<float4*>(g_nsum)[i] = z4;
    if (i < N4_IMG) {
        reinterpret_cast<uint4*>(g_dflat)[i] = make_uint4(big, big, big, big);
        reinterpret_cast<float4*>(g_ncnt)[i] = z4;
    }
    if (i < N4_LAST) reinterpret_cast<int4*>(g_last)[i] = make_int4(-1, -1, -1, -1);
    if (i < NVW) {
        g_dmin[i] = big; g_tmin[i] = big;
        g_dmax[i] = 0u;  g_tmax[i] = 0u;
        g_lsum[i] = 0.f; g_vcnt[i] = 0;
    }
}

// ------------- scatter: last-write-wins index per cell ---------------------
__global__ void k_scatter(const int4* __restrict__ coords, int n) {
    int i = blockIdx.x * blockDim.x + threadIdx.x;
    if (i >= n) return;
    int4 q = coords[i];                       // (.x=0, .y=c1, .z=c2, .w=c3)
    atomicMax(&g_last[(q.w * GD + q.z) * GD + q.y], i);
}

__global__ void k_grid(const float* __restrict__ sdf) {
    int c = blockIdx.x * blockDim.x + threadIdx.x;
    if (c >= NCELL) return;
    int idx = g_last[c];
    g_grid[c] = (idx >= 0) ? __ldg(&sdf[idx]) : 0.f;
}

// ---------------- per-view constants into shared ---------------------------
__device__ __forceinline__ void load_view_consts(const float* __restrict__ vm,
                                                 const float* __restrict__ intr,
                                                 float* s_vm, float* s_in) {
    int t = threadIdx.x;
    if (t < NVW * 12) s_vm[t] = vm[(t / 12) * 16 + (t % 12)];   // rows 0..2
    if (t < NVW * 4) {
        int v = t >> 2, k = t & 3;
        int off = (k == 0) ? 0 : (k == 1) ? 5 : (k == 2) ? 2 : 6; // fx,fy,cx,cy
        s_in[t] = intr[v * 16 + off];
    }
    __syncthreads();
}

// ------- pass 1: project (compute once, cache), z-buffer atomicMin ---------
__global__ void k_project(const int4* __restrict__ coords,
                          const float* __restrict__ origin,
                          const float* __restrict__ vm,
                          const float* __restrict__ intr, int n) {
    __shared__ float s_vm[NVW * 12];
    __shared__ float s_in[NVW * 4];
    load_view_consts(vm, intr, s_vm, s_in);
    int i = blockIdx.x * blockDim.x + threadIdx.x;
    if (i >= n) return;
    int4 q = coords[i];
    float px = __fadd_rn((float)q.w, __ldg(&origin[0]));
    float py = __fadd_rn((float)q.z, __ldg(&origin[1]));
    float pz = __fadd_rn((float)q.y, __ldg(&origin[2]));
    #pragma unroll
    for (int v = 0; v < NVW; v++) {
        const float* M = &s_vm[v * 12];
        float x = __fadd_rn(dotrow(M,     px, py, pz), M[3]);
        float y = __fadd_rn(dotrow(M + 4, px, py, pz), M[7]);
        float z = __fadd_rn(dotrow(M + 8, px, py, pz), M[11]);
        float zs = (fabsf(z) < 1e-6f) ? 1e-6f : z;
        int u = proj_pix(s_in[v*4+0], s_in[v*4+2], x, zs);
        int w = proj_pix(s_in[v*4+1], s_in[v*4+3], y, zs);
        bool valid = (z > 0.025f && z < 100.0f && u >= 0 && u < WSZ && w >= 0 && w < HSZ);
        int pix = valid ? (v * NPIX + w * WSZ + u) : -1;
        g_ppix[v * MAXN + i] = pix;
        g_pz[v * MAXN + i] = z;
        if (valid) atomicMin(&g_dflat[pix], __float_as_uint(z));
    }
}

// ------- pass 2: normals gather + winner test + normal splat ---------------
__global__ void k_splat(const int4* __restrict__ coords,
                        const float* __restrict__ vm,
                        const float* __restrict__ intr, int n) {
    __shared__ float s_vm[NVW * 12];
    __shared__ float s_in[NVW * 4];
    load_view_consts(vm, intr, s_vm, s_in);
    int i = blockIdx.x * blockDim.x + threadIdx.x;
    if (i >= n) return;
    int4 q = coords[i];
    int c1 = q.y, c2 = q.z, c3 = q.w;
    float na = 0.f, nb = 0.f, nc = 0.f;      // central-difference normal
    if (c3 >= 1 && c3 <= GD-2 && c2 >= 1 && c2 <= GD-2 && c1 >= 1 && c1 <= GD-2) {
        int base = (c3 * GD + c2) * GD + c1;
        na = __fsub_rn(g_grid[base + 1],     g_grid[base - 1]);
        nb = __fsub_rn(g_grid[base + GD],    g_grid[base - GD]);
        nc = __fsub_rn(g_grid[base + GD*GD], g_grid[base - GD*GD]);
    }
    #pragma unroll
    for (int v = 0; v < NVW; v++) {
        int pix = g_ppix[v * MAXN + i];
        if (pix < 0) continue;
        float z = g_pz[v * MAXN + i];
        float df = __uint_as_float(g_dflat[pix]);
        if (z <= __fadd_rn(df, 1e-6f)) {
            const float* M = &s_vm[v * 12];
            float rx = dotrow(M,     na, nb, nc);
            float ry = dotrow(M + 4, na, nb, nc);
            float rz = dotrow(M + 8, na, nb, nc);
            float ss = __fadd_rn(__fadd_rn(__fmul_rn(rx, rx), __fmul_rn(ry, ry)),
                                 __fmul_rn(rz, rz));
            float len = fmaxf(__fsqrt_rn(ss), 1e-5f);
            atomicAdd(&g_nsum[3*pix+0], __fdiv_rn(-rx, len));
            atomicAdd(&g_nsum[3*pix+1], __fdiv_rn(-ry, len));
            atomicAdd(&g_nsum[3*pix+2], __fdiv_rn(-rz, len));
            atomicAdd(&g_ncnt[pix], 1.f);
        }
    }
}

// ------- single reduction pass: min & max of both images + valid count -----
// (range = fsub(max,min) equals max(fsub(x,min)) by monotonicity of rn-sub)
__global__ void k_minmax(const float* __restrict__ tgt) {
    int v = blockIdx.y;
    int p = blockIdx.x * blockDim.x + threadIdx.x;   // NPIX % 256 == 0
    float df = __uint_as_float(g_dflat[v * NPIX + p]);
    float dimg = (df < 5e29f) ? __fmul_rn(df, 0.04f) : 0.f;
    float dt = tgt[v * NPIX + p];
    unsigned mnd = __float_as_uint(dimg), mxd = mnd;
    unsigned mnt = __float_as_uint(dt),  mxt = mnt;
    int cnt = (dt != 0.f) ? 1 : 0;
    for (int o = 16; o; o >>= 1) {
        mnd = min(mnd, __shfl_down_sync(0xffffffffu, mnd, o));
        mxd = max(mxd, __shfl_down_sync(0xffffffffu, mxd, o));
        mnt = min(mnt, __shfl_down_sync(0xffffffffu, mnt, o));
        mxt = max(mxt, __shfl_down_sync(0xffffffffu, mxt, o));
        cnt += __shfl_down_sync(0xffffffffu, cnt, o);
    }
    __shared__ unsigned smnd[8], smxd[8], smnt[8], smxt[8];
    __shared__ int sc[8];
    int wid = threadIdx.x >> 5, lid = threadIdx.x & 31;
    if (lid == 0) { smnd[wid]=mnd; smxd[wid]=mxd; smnt[wid]=mnt; smxt[wid]=mxt; sc[wid]=cnt; }
    __syncthreads();
    if (threadIdx.x == 0) {
        for (int w = 1; w < 8; w++) {
            mnd = min(mnd, smnd[w]); mxd = max(mxd, smxd[w]);
            mnt = min(mnt, smnt[w]); mxt = max(mxt, smxt[w]);
            cnt += sc[w];
        }
        atomicMin(&g_dmin[v], mnd); atomicMax(&g_dmax[v], mxd);
        atomicMin(&g_tmin[v], mnt); atomicMax(&g_tmax[v], mxt);
        atomicAdd(&g_vcnt[v], cnt);
    }
}

// ---------------- finalize images + partial loss ----------------------------
__global__ void k_final(const float* __restrict__ tgt, float* __restrict__ out) {
    int v = blockIdx.y;
    int p = blockIdx.x * blockDim.x + threadIdx.x;
    int gp = v * NPIX + p;
    float df = __uint_as_float(g_dflat[gp]);
    bool hit = df < 5e29f;
    float dimg = hit ? __fmul_rn(df, 0.04f) : 0.f;
    float dmn = __uint_as_float(g_dmin[v]);
    float sd  = __fsub_rn(dimg, dmn);
    float drg = __fsub_rn(__uint_as_float(g_dmax[v]), dmn);
    float dn = (drg != 0.f) ? __fdiv_rn(sd, drg) : sd;
    float dt = tgt[gp];
    float tmn = __uint_as_float(g_tmin[v]);
    float st  = __fsub_rn(dt, tmn);
    float trg = __fsub_rn(__uint_as_float(g_tmax[v]), tmn);
    float tn = (trg != 0.f) ? __fdiv_rn(st, trg) : st;
    out[1 + gp] = dn;
    out[1 + NVW * NPIX + gp] = tn;
    float cn = fmaxf(g_ncnt[gp], 1.f);
    out[1 + 2 * NVW * NPIX + 3 * gp + 0] = hit ? __fdiv_rn(g_nsum[3*gp+0], cn) : 0.f;
    out[1 + 2 * NVW * NPIX + 3 * gp + 1] = hit ? __fdiv_rn(g_nsum[3*gp+1], cn) : 0.f;
    out[1 + 2 * NVW * NPIX + 3 * gp + 2] = hit ? __fdiv_rn(g_nsum[3*gp+2], cn) : 0.f;
    float l = (dt != 0.f) ? fabsf(__fsub_rn(dn, tn)) : 0.f;
    for (int o = 16; o; o >>= 1) l += __shfl_down_sync(0xffffffffu, l, o);
    __shared__ float sl[8];
    int wid = threadIdx.x >> 5, lid = threadIdx.x & 31;
    if (lid == 0) sl[wid] = l;
    __syncthreads();
    if (threadIdx.x == 0) {
        for (int w = 1; w < 8; w++) l += sl[w];
        atomicAdd(&g_lsum[v], l);
    }
}

__global__ void k_loss(float* __restrict__ out) {
    if (threadIdx.x == 0) {
        float tot = 0.f;
        for (int v = 0; v < NVW; v++) {
            float c = (float)g_vcnt[v];
            float l = (g_vcnt[v] > 0) ? __fdiv_rn(g_lsum[v], fmaxf(c, 1.f)) : 0.f;
            tot = __fadd_rn(tot, __fdiv_rn(l, 9.0f));   // * WEIGHT(1) / N_VIEWS
        }
        out[0] = tot;
    }
}

// ---------------------------------------------------------------------------
extern "C" void kernel_launch(void* const* d_in, const int* in_sizes, int n_in,
                              void* d_out, int out_size) {
    const int4*  coords = (const int4*) d_in[0];
    const float* origin = (const float*)d_in[1];
    const float* sdf    = (const float*)d_in[2];
    // d_in[3] = sdf_target (unused by forward)
    const float* tgt    = (const float*)d_in[4];
    const float* intr   = (const float*)d_in[5];
    const float* vm     = (const float*)d_in[6];
    float* out = (float*)d_out;

    int n = in_sizes[0] / 4;
    if (n > MAXN) n = MAXN;
    const int tb = 256;

    k_init<<<(N4_NSUM + tb - 1) / tb, tb>>>();
    k_scatter<<<(n + tb - 1) / tb, tb>>>(coords, n);
    k_grid<<<(NCELL + tb - 1) / tb, tb>>>(sdf);
    k_project<<<(n + tb - 1) / tb, tb>>>(coords, origin, vm, intr, n);
    k_splat<<<(n + tb - 1) / tb, tb>>>(coords, vm, intr, n);
    dim3 rg(NPIX / tb, NVW);
    k_minmax<<<rg, tb>>>(tgt);
    k_final<<<rg, tb>>>(tgt, out);
    k_loss<<<1, 32>>>(out);
}

// round 6
// speedup vs baseline: 1.1848x; 1.1848x over previous
#include <cuda_runtime.h>

#define NVW   9
#define HSZ   480
#define WSZ   640
#define NPIX  (HSZ*WSZ)
#define GD    96
#define NCELL (GD*GD*GD)
#define PIXB  (NPIX/256)     // 1200 blocks per view image
#define GRIDB (NCELL/256)    // 3456 blocks for voxel grid

// ==== zero-canonical scratch: .bss zero state == canonical empty state, ====
// ==== and every consumer kernel restores the state it consumed.        ====
__device__ __align__(16) int          g_last[NCELL];        // idx+1, 0 = empty
__device__ float                      g_grid[NCELL];        // fully rewritten each call
__device__ __align__(16) unsigned int g_dflat[NVW*NPIX];    // ~bits(z), atomicMax == min-z, 0 = no hit
__device__ __align__(16) float4       g_ns4[NVW*NPIX];      // xyz=nsum, w=ncnt, zero-canonical
__device__ unsigned int g_dminE[NVW], g_tminE[NVW];          // ~bits of min, atomicMax, 0-canonical
__device__ unsigned int g_dmax[NVW],  g_tmax[NVW];           // bits of max (vals>=0), 0-canonical
__device__ float        g_lsum[NVW];
__device__ int          g_vcnt[NVW];

// XLA:CPU dot (no FMA contraction, left-assoc, strict rn): ((p0*m0 + p1*m1) + p2*m2)
__device__ __forceinline__ float dotrow(const float* M, float px, float py, float pz) {
    return __fadd_rn(__fadd_rn(__fmul_rn(px, M[0]), __fmul_rn(py, M[1])),
                     __fmul_rn(pz, M[2]));
}
// u = rn( (f*x)/zs + c ), strict
__device__ __forceinline__ int proj_pix(float f, float c, float x, float zs) {
    return __float2int_rn(__fadd_rn(__fdiv_rn(__fmul_rn(f, x), zs), c));
}

__device__ __forceinline__ void load_view_consts(const float* __restrict__ vm,
                                                 const float* __restrict__ intr,
                                                 float* s_vm, float* s_in) {
    int t = threadIdx.x;
    if (t < NVW * 12) s_vm[t] = vm[(t / 12) * 16 + (t % 12)];   // rows 0..2 of 4x4
    if (t < NVW * 4) {
        int v = t >> 2, k = t & 3;
        int off = (k == 0) ? 0 : (k == 1) ? 5 : (k == 2) ? 2 : 6; // fx,fy,cx,cy
        s_in[t] = intr[v * 16 + off];
    }
    __syncthreads();
}

// ---------------- L1: scatter (last-write-wins via idx+1) ------------------
__global__ void k_scatter(const int4* __restrict__ coords, int n) {
    int i = blockIdx.x * blockDim.x + threadIdx.x;
    if (i >= n) return;
    int4 q = coords[i];                        // (.x=0, .y=c1, .z=c2, .w=c3)
    atomicMax(&g_last[(q.w * GD + q.z) * GD + q.y], i + 1);
}

// ------ L2 fused: [0,GRIDB) grid materialize+reset ; [GRIDB,..) project ----
__global__ void k_grid_project(const int4* __restrict__ coords,
                               const float* __restrict__ origin,
                               const float* __restrict__ vm,
                               const float* __restrict__ intr,
                               const float* __restrict__ sdf, int n) {
    if (blockIdx.x < GRIDB) {
        int c = blockIdx.x * blockDim.x + threadIdx.x;
        int idx = g_last[c];
        g_grid[c] = (idx > 0) ? __ldg(&sdf[idx - 1]) : 0.f;
        g_last[c] = 0;                                   // self-clean
        return;
    }
    __shared__ float s_vm[NVW * 12];
    __shared__ float s_in[NVW * 4];
    load_view_consts(vm, intr, s_vm, s_in);
    int i = (blockIdx.x - GRIDB) * blockDim.x + threadIdx.x;
    if (i >= n) return;
    int4 q = coords[i];
    float px = __fadd_rn((float)q.w, __ldg(&origin[0]));
    float py = __fadd_rn((float)q.z, __ldg(&origin[1]));
    float pz = __fadd_rn((float)q.y, __ldg(&origin[2]));
    #pragma unroll
    for (int v = 0; v < NVW; v++) {
        const float* M = &s_vm[v * 12];
        float x = __fadd_rn(dotrow(M,     px, py, pz), M[3]);
        float y = __fadd_rn(dotrow(M + 4, px, py, pz), M[7]);
        float z = __fadd_rn(dotrow(M + 8, px, py, pz), M[11]);
        float zs = (fabsf(z) < 1e-6f) ? 1e-6f : z;
        int u = proj_pix(s_in[v*4+0], s_in[v*4+2], x, zs);
        int w = proj_pix(s_in[v*4+1], s_in[v*4+3], y, zs);
        if (z > 0.025f && z < 100.0f && u >= 0 && u < WSZ && w >= 0 && w < HSZ)
            atomicMin: ;
        if (z > 0.025f && z < 100.0f && u >= 0 && u < WSZ && w >= 0 && w < HSZ)
            atomicMax(&g_dflat[v * NPIX + w * WSZ + u], ~__float_as_uint(z));
    }
}

// ------ L3 fused: [0,projB) splat ; [projB, projB+9*PIXB) image minmax -----
__global__ void k_splat_minmax(const int4* __restrict__ coords,
                               const float* __restrict__ origin,
                               const float* __restrict__ vm,
                               const float* __restrict__ intr,
                               const float* __restrict__ tgt, int n, int projB) {
    if ((int)blockIdx.x < projB) {
        __shared__ float s_vm[NVW * 12];
        __shared__ float s_in[NVW * 4];
        load_view_consts(vm, intr, s_vm, s_in);
        int i = blockIdx.x * blockDim.x + threadIdx.x;
        if (i >= n) return;
        int4 q = coords[i];
        float px = __fadd_rn((float)q.w, __ldg(&origin[0]));
        float py = __fadd_rn((float)q.z, __ldg(&origin[1]));
        float pz = __fadd_rn((float)q.y, __ldg(&origin[2]));
        float na = 0.f, nb = 0.f, nc = 0.f;
        if (q.w >= 1 && q.w <= GD-2 && q.z >= 1 && q.z <= GD-2 && q.y >= 1 && q.y <= GD-2) {
            int base = (q.w * GD + q.z) * GD + q.y;
            na = __fsub_rn(g_grid[base + 1],     g_grid[base - 1]);
            nb = __fsub_rn(g_grid[base + GD],    g_grid[base - GD]);
            nc = __fsub_rn(g_grid[base + GD*GD], g_grid[base - GD*GD]);
        }
        #pragma unroll
        for (int v = 0; v < NVW; v++) {
            const float* M = &s_vm[v * 12];
            float x = __fadd_rn(dotrow(M,     px, py, pz), M[3]);
            float y = __fadd_rn(dotrow(M + 4, px, py, pz), M[7]);
            float z = __fadd_rn(dotrow(M + 8, px, py, pz), M[11]);
            float zs = (fabsf(z) < 1e-6f) ? 1e-6f : z;
            int u = proj_pix(s_in[v*4+0], s_in[v*4+2], x, zs);
            int w = proj_pix(s_in[v*4+1], s_in[v*4+3], y, zs);
            if (!(z > 0.025f && z < 100.0f && u >= 0 && u < WSZ && w >= 0 && w < HSZ))
                continue;
            int pix = v * NPIX + w * WSZ + u;
            float df = __uint_as_float(~g_dflat[pix]);   // exact min-z (bit round-trip)
            if (z <= __fadd_rn(df, 1e-6f)) {
                float rx = dotrow(M,     na, nb, nc);
                float ry = dotrow(M + 4, na, nb, nc);
                float rz = dotrow(M + 8, na, nb, nc);
                float ss = __fadd_rn(__fadd_rn(__fmul_rn(rx, rx), __fmul_rn(ry, ry)),
                                     __fmul_rn(rz, rz));
                float len = fmaxf(__fsqrt_rn(ss), 1e-5f);
                float* base = &g_ns4[pix].x;
                atomicAdd(base + 0, __fdiv_rn(-rx, len));
                atomicAdd(base + 1, __fdiv_rn(-ry, len));
                atomicAdd(base + 2, __fdiv_rn(-rz, len));
                atomicAdd(base + 3, 1.f);
            }
        }
        return;
    }
    // ---- minmax part: per-view min/max of both images + valid count ----
    int b = blockIdx.x - projB;
    int v = b / PIXB;
    int p = (b % PIXB) * blockDim.x + threadIdx.x;
    unsigned raw = g_dflat[v * NPIX + p];
    float dimg = raw ? __fmul_rn(__uint_as_float(~raw), 0.04f) : 0.f;
    float dt = tgt[v * NPIX + p];
    float mnd = dimg, mxd = dimg, mnt = dt, mxt = dt;
    int cnt = (dt != 0.f) ? 1 : 0;
    for (int o = 16; o; o >>= 1) {
        mnd = fminf(mnd, __shfl_down_sync(0xffffffffu, mnd, o));
        mxd = fmaxf(mxd, __shfl_down_sync(0xffffffffu, mxd, o));
        mnt = fminf(mnt, __shfl_down_sync(0xffffffffu, mnt, o));
        mxt = fmaxf(mxt, __shfl_down_sync(0xffffffffu, mxt, o));
        cnt += __shfl_down_sync(0xffffffffu, cnt, o);
    }
    __shared__ float smnd[8], smxd[8], smnt[8], smxt[8];
    __shared__ int sc[8];
    int wid = threadIdx.x >> 5, lid = threadIdx.x & 31;
    if (lid == 0) { smnd[wid]=mnd; smxd[wid]=mxd; smnt[wid]=mnt; smxt[wid]=mxt; sc[wid]=cnt; }
    __syncthreads();
    if (threadIdx.x == 0) {
        for (int w = 1; w < 8; w++) {
            mnd = fminf(mnd, smnd[w]); mxd = fmaxf(mxd, smxd[w]);
            mnt = fminf(mnt, smnt[w]); mxt = fmaxf(mxt, smxt[w]);
            cnt += sc[w];
        }
        atomicMax(&g_dminE[v], ~__float_as_uint(mnd));   // encoded min (0-canonical)
        atomicMax(&g_dmax[v],   __float_as_uint(mxd));
        atomicMax(&g_tminE[v], ~__float_as_uint(mnt));
        atomicMax(&g_tmax[v],   __float_as_uint(mxt));
        atomicAdd(&g_vcnt[v], cnt);
    }
}

// ---------------- L4: finalize images + partial loss + self-clean ----------
__global__ void k_final(const float* __restrict__ tgt, float* __restrict__ out) {
    int v = blockIdx.y;
    int p = blockIdx.x * blockDim.x + threadIdx.x;
    int gp = v * NPIX + p;
    unsigned raw = g_dflat[gp];
    bool hit = raw != 0u;
    float dimg = hit ? __fmul_rn(__uint_as_float(~raw), 0.04f) : 0.f;
    float dmn = __uint_as_float(~g_dminE[v]);
    float sd  = __fsub_rn(dimg, dmn);
    float drg = __fsub_rn(__uint_as_float(g_dmax[v]), dmn);
    float dn = (drg != 0.f) ? __fdiv_rn(sd, drg) : sd;
    float dt = tgt[gp];
    float tmn = __uint_as_float(~g_tminE[v]);
    float st  = __fsub_rn(dt, tmn);
    float trg = __fsub_rn(__uint_as_float(g_tmax[v]), tmn);
    float tn = (trg != 0.f) ? __fdiv_rn(st, trg) : st;
    out[1 + gp] = dn;
    out[1 + NVW * NPIX + gp] = tn;
    float4 ns = g_ns4[gp];
    float cn = fmaxf(ns.w, 1.f);
    out[1 + 2 * NVW * NPIX + 3 * gp + 0] = hit ? __fdiv_rn(ns.x, cn) : 0.f;
    out[1 + 2 * NVW * NPIX + 3 * gp + 1] = hit ? __fdiv_rn(ns.y, cn) : 0.f;
    out[1 + 2 * NVW * NPIX + 3 * gp + 2] = hit ? __fdiv_rn(ns.z, cn) : 0.f;
    g_ns4[gp] = make_float4(0.f, 0.f, 0.f, 0.f);   // self-clean
    g_dflat[gp] = 0u;                              // self-clean
    float l = (dt != 0.f) ? fabsf(__fsub_rn(dn, tn)) : 0.f;
    for (int o = 16; o; o >>= 1) l += __shfl_down_sync(0xffffffffu, l, o);
    __shared__ float sl[8];
    int wid = threadIdx.x >> 5, lid = threadIdx.x & 31;
    if (lid == 0) sl[wid] = l;
    __syncthreads();
    if (threadIdx.x == 0) {
        for (int w = 1; w < 8; w++) l += sl[w];
        atomicAdd(&g_lsum[v], l);
    }
}

// ---------------- L5: loss + scalar self-clean ------------------------------
__global__ void k_loss(float* __restrict__ out) {
    if (threadIdx.x == 0) {
        float tot = 0.f;
        for (int v = 0; v < NVW; v++) {
            float c = (float)g_vcnt[v];
            float l = (g_vcnt[v] > 0) ? __fdiv_rn(g_lsum[v], fmaxf(c, 1.f)) : 0.f;
            tot = __fadd_rn(tot, __fdiv_rn(l, 9.0f));   // * WEIGHT(1) / N_VIEWS
            g_lsum[v] = 0.f; g_vcnt[v] = 0;             // self-clean
            g_dminE[v] = 0u; g_tminE[v] = 0u;
            g_dmax[v] = 0u;  g_tmax[v] = 0u;
        }
        out[0] = tot;
    }
}

// ---------------------------------------------------------------------------
extern "C" void kernel_launch(void* const* d_in, const int* in_sizes, int n_in,
                              void* d_out, int out_size) {
    const int4*  coords = (const int4*) d_in[0];
    const float* origin = (const float*)d_in[1];
    const float* sdf    = (const float*)d_in[2];
    // d_in[3] = sdf_target (unused by forward)
    const float* tgt    = (const float*)d_in[4];
    const float* intr   = (const float*)d_in[5];
    const float* vm     = (const float*)d_in[6];
    float* out = (float*)d_out;

    int n = in_sizes[0] / 4;
    const int tb = 256;
    int projB = (n + tb - 1) / tb;

    k_scatter<<<projB, tb>>>(coords, n);
    k_grid_project<<<GRIDB + projB, tb>>>(coords, origin, vm, intr, sdf, n);
    k_splat_minmax<<<projB + NVW * PIXB, tb>>>(coords, origin, vm, intr, tgt, n, projB);
    dim3 rg(PIXB, NVW);
    k_final<<<rg, tb>>>(tgt, out);
    k_loss<<<1, 32>>>(out);
}

// round 7
// speedup vs baseline: 1.3588x; 1.1469x over previous
#include <cuda_runtime.h>

#define NVW   9
#define HSZ   480
#define WSZ   640
#define NPIX  (HSZ*WSZ)
#define GD    96
#define NCELL (GD*GD*GD)
#define PIXB4 (NPIX/(256*4))   // 300 blocks per view image, 4 px/thread
#define GRIDB (NCELL/256)      // 3456 blocks for voxel grid

// ==== zero-canonical scratch: .bss zero state == canonical empty state, ====
// ==== and every consumer kernel restores the state it consumed.        ====
__device__ __align__(16) int          g_last[NCELL];        // idx+1, 0 = empty
__device__ float                      g_grid[NCELL];        // fully rewritten each call
__device__ __align__(16) unsigned int g_dflat[NVW*NPIX];    // ~bits(z), atomicMax == min-z, 0 = no hit
__device__ __align__(16) float4       g_ns4[NVW*NPIX];      // xyz=nsum, w=ncnt, zero-canonical
__device__ unsigned int g_dminE[NVW], g_tminE[NVW];          // ~bits of min, atomicMax, 0-canonical
__device__ unsigned int g_dmax[NVW],  g_tmax[NVW];           // bits of max (vals>=0), 0-canonical
__device__ float        g_lsum[NVW];
__device__ int          g_vcnt[NVW];

// XLA:CPU dot (no FMA contraction, left-assoc, strict rn): ((p0*m0 + p1*m1) + p2*m2)
__device__ __forceinline__ float dotrow(const float* M, float px, float py, float pz) {
    return __fadd_rn(__fadd_rn(__fmul_rn(px, M[0]), __fmul_rn(py, M[1])),
                     __fmul_rn(pz, M[2]));
}
// u = rn( (f*x)/zs + c ), strict
__device__ __forceinline__ int proj_pix(float f, float c, float x, float zs) {
    return __float2int_rn(__fadd_rn(__fdiv_rn(__fmul_rn(f, x), zs), c));
}

__device__ __forceinline__ void load_view_consts(const float* __restrict__ vm,
                                                 const float* __restrict__ intr,
                                                 float* s_vm, float* s_in) {
    int t = threadIdx.x;
    if (t < NVW * 12) s_vm[t] = vm[(t / 12) * 16 + (t % 12)];   // rows 0..2 of 4x4
    if (t < NVW * 4) {
        int v = t >> 2, k = t & 3;
        int off = (k == 0) ? 0 : (k == 1) ? 5 : (k == 2) ? 2 : 6; // fx,fy,cx,cy
        s_in[t] = intr[v * 16 + off];
    }
    __syncthreads();
}

// ---- L1 fused: [0,projB) scatter ; [projB,..) target-image min/max/count --
__global__ void k_scatter_tmm(const int4* __restrict__ coords,
                              const float* __restrict__ tgt, int n, int projB) {
    if ((int)blockIdx.x < projB) {
        int i = blockIdx.x * blockDim.x + threadIdx.x;
        if (i >= n) return;
        int4 q = coords[i];                    // (.x=0, .y=c1, .z=c2, .w=c3)
        atomicMax(&g_last[(q.w * GD + q.z) * GD + q.y], i + 1);  // last-write-wins
        return;
    }
    int b = blockIdx.x - projB;
    int v = b / PIXB4;
    int p4 = (b % PIXB4) * blockDim.x + threadIdx.x;
    float4 dt = reinterpret_cast<const float4*>(tgt)[v * (NPIX/4) + p4];
    float mnt = fminf(fminf(dt.x, dt.y), fminf(dt.z, dt.w));
    float mxt = fmaxf(fmaxf(dt.x, dt.y), fmaxf(dt.z, dt.w));
    int cnt = (dt.x != 0.f) + (dt.y != 0.f) + (dt.z != 0.f) + (dt.w != 0.f);
    for (int o = 16; o; o >>= 1) {
        mnt = fminf(mnt, __shfl_down_sync(0xffffffffu, mnt, o));
        mxt = fmaxf(mxt, __shfl_down_sync(0xffffffffu, mxt, o));
        cnt += __shfl_down_sync(0xffffffffu, cnt, o);
    }
    __shared__ float smnt[8], smxt[8];
    __shared__ int sc[8];
    int wid = threadIdx.x >> 5, lid = threadIdx.x & 31;
    if (lid == 0) { smnt[wid] = mnt; smxt[wid] = mxt; sc[wid] = cnt; }
    __syncthreads();
    if (threadIdx.x == 0) {
        for (int w = 1; w < 8; w++) {
            mnt = fminf(mnt, smnt[w]); mxt = fmaxf(mxt, smxt[w]); cnt += sc[w];
        }
        atomicMax(&g_tminE[v], ~__float_as_uint(mnt));   // encoded min (0-canonical)
        atomicMax(&g_tmax[v],   __float_as_uint(mxt));
        atomicAdd(&g_vcnt[v], cnt);
    }
}

// ------ L2 fused: [0,GRIDB) grid materialize+reset ; [GRIDB,..) project ----
__global__ void k_grid_project(const int4* __restrict__ coords,
                               const float* __restrict__ origin,
                               const float* __restrict__ vm,
                               const float* __restrict__ intr,
                               const float* __restrict__ sdf, int n) {
    if (blockIdx.x < GRIDB) {
        int c = blockIdx.x * blockDim.x + threadIdx.x;
        int idx = g_last[c];
        g_grid[c] = (idx > 0) ? __ldg(&sdf[idx - 1]) : 0.f;
        if (idx > 0) g_last[c] = 0;                     // self-clean (skip if clean)
        return;
    }
    __shared__ float s_vm[NVW * 12];
    __shared__ float s_in[NVW * 4];
    load_view_consts(vm, intr, s_vm, s_in);
    int i = (blockIdx.x - GRIDB) * blockDim.x + threadIdx.x;
    if (i >= n) return;
    int4 q = coords[i];
    float px = __fadd_rn((float)q.w, __ldg(&origin[0]));
    float py = __fadd_rn((float)q.z, __ldg(&origin[1]));
    float pz = __fadd_rn((float)q.y, __ldg(&origin[2]));
    #pragma unroll
    for (int v = 0; v < NVW; v++) {
        const float* M = &s_vm[v * 12];
        float x = __fadd_rn(dotrow(M,     px, py, pz), M[3]);
        float y = __fadd_rn(dotrow(M + 4, px, py, pz), M[7]);
        float z = __fadd_rn(dotrow(M + 8, px, py, pz), M[11]);
        float zs = (fabsf(z) < 1e-6f) ? 1e-6f : z;
        int u = proj_pix(s_in[v*4+0], s_in[v*4+2], x, zs);
        int w = proj_pix(s_in[v*4+1], s_in[v*4+3], y, zs);
        if (z > 0.025f && z < 100.0f && u >= 0 && u < WSZ && w >= 0 && w < HSZ)
            atomicMax(&g_dflat[v * NPIX + w * WSZ + u], ~__float_as_uint(z));
    }
}

// ------ L3 fused: [0,projB) splat ; [projB,..) depth-image minmax ----------
__global__ void k_splat_dmm(const int4* __restrict__ coords,
                            const float* __restrict__ origin,
                            const float* __restrict__ vm,
                            const float* __restrict__ intr, int n, int projB) {
    if ((int)blockIdx.x < projB) {
        __shared__ float s_vm[NVW * 12];
        __shared__ float s_in[NVW * 4];
        load_view_consts(vm, intr, s_vm, s_in);
        int i = blockIdx.x * blockDim.x + threadIdx.x;
        if (i >= n) return;
        int4 q = coords[i];
        float px = __fadd_rn((float)q.w, __ldg(&origin[0]));
        float py = __fadd_rn((float)q.z, __ldg(&origin[1]));
        float pz = __fadd_rn((float)q.y, __ldg(&origin[2]));
        float na = 0.f, nb = 0.f, nc = 0.f;
        if (q.w >= 1 && q.w <= GD-2 && q.z >= 1 && q.z <= GD-2 && q.y >= 1 && q.y <= GD-2) {
            int base = (q.w * GD + q.z) * GD + q.y;
            na = __fsub_rn(g_grid[base + 1],     g_grid[base - 1]);
            nb = __fsub_rn(g_grid[base + GD],    g_grid[base - GD]);
            nc = __fsub_rn(g_grid[base + GD*GD], g_grid[base - GD*GD]);
        }
        #pragma unroll
        for (int v = 0; v < NVW; v++) {
            const float* M = &s_vm[v * 12];
            float x = __fadd_rn(dotrow(M,     px, py, pz), M[3]);
            float y = __fadd_rn(dotrow(M + 4, px, py, pz), M[7]);
            float z = __fadd_rn(dotrow(M + 8, px, py, pz), M[11]);
            float zs = (fabsf(z) < 1e-6f) ? 1e-6f : z;
            int u = proj_pix(s_in[v*4+0], s_in[v*4+2], x, zs);
            int w = proj_pix(s_in[v*4+1], s_in[v*4+3], y, zs);
            if (!(z > 0.025f && z < 100.0f && u >= 0 && u < WSZ && w >= 0 && w < HSZ))
                continue;
            int pix = v * NPIX + w * WSZ + u;
            float df = __uint_as_float(~g_dflat[pix]);   // exact min-z (bit round-trip)
            if (z <= __fadd_rn(df, 1e-6f)) {
                float rx = dotrow(M,     na, nb, nc);
                float ry = dotrow(M + 4, na, nb, nc);
                float rz = dotrow(M + 8, na, nb, nc);
                float ss = __fadd_rn(__fadd_rn(__fmul_rn(rx, rx), __fmul_rn(ry, ry)),
                                     __fmul_rn(rz, rz));
                float len = fmaxf(__fsqrt_rn(ss), 1e-5f);
                float* base = &g_ns4[pix].x;
                atomicAdd(base + 0, __fdiv_rn(-rx, len));
                atomicAdd(base + 1, __fdiv_rn(-ry, len));
                atomicAdd(base + 2, __fdiv_rn(-rz, len));
                atomicAdd(base + 3, 1.f);
            }
        }
        return;
    }
    // ---- depth-image min/max (float4-vectorized) ----
    int b = blockIdx.x - projB;
    int v = b / PIXB4;
    int p4 = (b % PIXB4) * blockDim.x + threadIdx.x;
    uint4 raw = reinterpret_cast<const uint4*>(g_dflat)[v * (NPIX/4) + p4];
    float d0 = raw.x ? __fmul_rn(__uint_as_float(~raw.x), 0.04f) : 0.f;
    float d1 = raw.y ? __fmul_rn(__uint_as_float(~raw.y), 0.04f) : 0.f;
    float d2 = raw.z ? __fmul_rn(__uint_as_float(~raw.z), 0.04f) : 0.f;
    float d3 = raw.w ? __fmul_rn(__uint_as_float(~raw.w), 0.04f) : 0.f;
    float mnd = fminf(fminf(d0, d1), fminf(d2, d3));
    float mxd = fmaxf(fmaxf(d0, d1), fmaxf(d2, d3));
    for (int o = 16; o; o >>= 1) {
        mnd = fminf(mnd, __shfl_down_sync(0xffffffffu, mnd, o));
        mxd = fmaxf(mxd, __shfl_down_sync(0xffffffffu, mxd, o));
    }
    __shared__ float smnd[8], smxd[8];
    int wid = threadIdx.x >> 5, lid = threadIdx.x & 31;
    if (lid == 0) { smnd[wid] = mnd; smxd[wid] = mxd; }
    __syncthreads();
    if (threadIdx.x == 0) {
        for (int w = 1; w < 8; w++) { mnd = fminf(mnd, smnd[w]); mxd = fmaxf(mxd, smxd[w]); }
        atomicMax(&g_dminE[v], ~__float_as_uint(mnd));
        atomicMax(&g_dmax[v],   __float_as_uint(mxd));
    }
}

// ---------------- L4: finalize images + partial loss + self-clean ----------
__global__ void k_final(const float* __restrict__ tgt, float* __restrict__ out) {
    int v = blockIdx.y;
    int p = blockIdx.x * blockDim.x + threadIdx.x;
    int gp = v * NPIX + p;
    unsigned raw = g_dflat[gp];
    bool hit = raw != 0u;
    float dimg = hit ? __fmul_rn(__uint_as_float(~raw), 0.04f) : 0.f;
    float dmn = __uint_as_float(~g_dminE[v]);
    float sd  = __fsub_rn(dimg, dmn);
    float drg = __fsub_rn(__uint_as_float(g_dmax[v]), dmn);
    float dn = (drg != 0.f) ? __fdiv_rn(sd, drg) : sd;
    float dt = tgt[gp];
    float tmn = __uint_as_float(~g_tminE[v]);
    float st  = __fsub_rn(dt, tmn);
    float trg = __fsub_rn(__uint_as_float(g_tmax[v]), tmn);
    float tn = (trg != 0.f) ? __fdiv_rn(st, trg) : st;
    __stcs(&out[1 + gp], dn);                          // streaming: don't pollute L2
    __stcs(&out[1 + NVW * NPIX + gp], tn);
    if (hit) {                                         // !hit => ns4 provably zero
        float4 ns = g_ns4[gp];
        float cn = fmaxf(ns.w, 1.f);
        __stcs(&out[1 + 2 * NVW * NPIX + 3 * gp + 0], __fdiv_rn(ns.x, cn));
        __stcs(&out[1 + 2 * NVW * NPIX + 3 * gp + 1], __fdiv_rn(ns.y, cn));
        __stcs(&out[1 + 2 * NVW * NPIX + 3 * gp + 2], __fdiv_rn(ns.z, cn));
        g_ns4[gp] = make_float4(0.f, 0.f, 0.f, 0.f);   // self-clean
        g_dflat[gp] = 0u;                              // self-clean
    } else {
        __stcs(&out[1 + 2 * NVW * NPIX + 3 * gp + 0], 0.f);
        __stcs(&out[1 + 2 * NVW * NPIX + 3 * gp + 1], 0.f);
        __stcs(&out[1 + 2 * NVW * NPIX + 3 * gp + 2], 0.f);
    }
    float l = (dt != 0.f) ? fabsf(__fsub_rn(dn, tn)) : 0.f;
    for (int o = 16; o; o >>= 1) l += __shfl_down_sync(0xffffffffu, l, o);
    __shared__ float sl[8];
    int wid = threadIdx.x >> 5, lid = threadIdx.x & 31;
    if (lid == 0) sl[wid] = l;
    __syncthreads();
    if (threadIdx.x == 0) {
        for (int w = 1; w < 8; w++) l += sl[w];
        atomicAdd(&g_lsum[v], l);
    }
}

// ---------------- L5: loss + scalar self-clean ------------------------------
__global__ void k_loss(float* __restrict__ out) {
    if (threadIdx.x == 0) {
        float tot = 0.f;
        for (int v = 0; v < NVW; v++) {
            float c = (float)g_vcnt[v];
            float l = (g_vcnt[v] > 0) ? __fdiv_rn(g_lsum[v], fmaxf(c, 1.f)) : 0.f;
            tot = __fadd_rn(tot, __fdiv_rn(l, 9.0f));   // * WEIGHT(1) / N_VIEWS
            g_lsum[v] = 0.f; g_vcnt[v] = 0;             // self-clean
            g_dminE[v] = 0u; g_tminE[v] = 0u;
            g_dmax[v] = 0u;  g_tmax[v] = 0u;
        }
        out[0] = tot;
    }
}

// ---------------------------------------------------------------------------
extern "C" void kernel_launch(void* const* d_in, const int* in_sizes, int n_in,
                              void* d_out, int out_size) {
    const int4*  coords = (const int4*) d_in[0];
    const float* origin = (const float*)d_in[1];
    const float* sdf    = (const float*)d_in[2];
    // d_in[3] = sdf_target (unused by forward)
    const float* tgt    = (const float*)d_in[4];
    const float* intr   = (const float*)d_in[5];
    const float* vm     = (const float*)d_in[6];
    float* out = (float*)d_out;

    int n = in_sizes[0] / 4;
    const int tb = 256;
    int projB = (n + tb - 1) / tb;

    k_scatter_tmm<<<projB + NVW * PIXB4, tb>>>(coords, tgt, n, projB);
    k_grid_project<<<GRIDB + projB, tb>>>(coords, origin, vm, intr, sdf, n);
    k_splat_dmm<<<projB + NVW * PIXB4, tb>>>(coords, origin, vm, intr, n, projB);
    dim3 rg(NPIX / tb, NVW);
    k_final<<<rg, tb>>>(tgt, out);
    k_loss<<<1, 32>>>(out);
}